// round 5
// baseline (speedup 1.0000x reference)
#include <cuda_runtime.h>
#include <cuda_fp16.h>
#include <mma.h>
#include <math.h>

using namespace nvcuda;

#define NN 100000
#define NE 1600000
#define NV 15000
#define DD 128
#define NG 16
#define NPAD 100352                 // 98 * 1024
#define NSCB 98                     // scan blocks (1024 counts each)

// ---------------- device scratch (static: no allocations allowed) ------------
__device__ int    g_off[NPAD + 4];
__device__ int    g_cursor[NPAD + 4];
__device__ unsigned long long g_state[NSCB];   // lookback scan state
__device__ int2   g_meta[NE];                  // {(wid<<17)|src, bits(w*norm[src])}
__device__ __half g_Ph[NV * DD];               // embeds @ W0 fp16 (L2-resident)
__device__ __half g_H0h[NN * DD];              // layer-1 output fp16
__device__ __half g_W0h[DD * DD];
__device__ __half g_W1h[DD * DD];
__device__ float  g_pool[NG * DD];             // per-graph max (relu>=0 -> int cmp)

// ---------------- helpers ----------------------------------------------------
__device__ __forceinline__ void split_h2(float2 raw, float2& f0, float2& f1) {
    __half2 h0 = *reinterpret_cast<__half2*>(&raw.x);
    __half2 h1 = *reinterpret_cast<__half2*>(&raw.y);
    f0 = __half22float2(h0);
    f1 = __half22float2(h1);
}

// ---------------- 0: zero + W conversions ------------------------------------
__global__ void k_zero(const float* __restrict__ W0, const float* __restrict__ W1) {
    int i = blockIdx.x * 256 + threadIdx.x;
    if (i < NPAD + 4) g_off[i] = 0;
    if (i < NG * DD) g_pool[i] = 0.0f;
    if (i < NSCB) g_state[i] = 0ull;
    if (i < DD * DD) {
        g_W0h[i] = __float2half(W0[i]);
        g_W1h[i] = __float2half(W1[i]);
    }
}

// ---------------- 1: histogram -----------------------------------------------
__global__ void k_hist(const int* __restrict__ edst) {
    int e = blockIdx.x * 256 + threadIdx.x;
    if (e < NE) atomicAdd(&g_off[edst[e]], 1);
}

// ---------------- 2: single-pass scan (decoupled lookback, 98 blocks) --------
__global__ __launch_bounds__(256) void k_scan() {
    __shared__ int sm[256];
    __shared__ int s_prefix;
    int b = blockIdx.x, t = threadIdx.x;
    int4 c = ((const int4*)g_off)[b * 256 + t];
    int s = c.x + c.y + c.z + c.w;
    sm[t] = s;
    __syncthreads();
    // inclusive Hillis-Steele
    for (int off = 1; off < 256; off <<= 1) {
        int u = (t >= off) ? sm[t - off] : 0;
        __syncthreads();
        sm[t] += u;
        __syncthreads();
    }
    int total = sm[255];
    int excl = sm[t] - s;

    if (t == 0) {
        if (b == 0) {
            __threadfence();
            atomicExch(&g_state[0], (2ull << 62) | (unsigned)total);
            s_prefix = 0;
        } else {
            __threadfence();
            atomicExch(&g_state[b], (1ull << 62) | (unsigned)total);
            long long run = 0;
            int p = b - 1;
            while (true) {
                unsigned long long st = atomicAdd(&g_state[p], 0ull);
                unsigned long long flag = st >> 62;
                if (flag == 0ull) continue;            // spin
                int val = (int)(st & 0xffffffffull);
                run += val;
                if (flag == 2ull) break;               // inclusive prefix found
                p--;
            }
            s_prefix = (int)run;
            __threadfence();
            atomicExch(&g_state[b], (2ull << 62) | (unsigned)(run + total));
        }
    }
    __syncthreads();
    int base = s_prefix + excl;
    int4 o;
    o.x = base;
    o.y = base + c.x;
    o.z = o.y + c.y;
    o.w = o.z + c.z;
    ((int4*)g_off)[b * 256 + t] = o;
    ((int4*)g_cursor)[b * 256 + t] = o;
}

// ---------------- 3: scatter --------------------------------------------------
__global__ void k_scatter(const int* __restrict__ esrc, const int* __restrict__ edst,
                          const float* __restrict__ ew, const float* __restrict__ norm,
                          const int* __restrict__ word_ids) {
    int e = blockIdx.x * 256 + threadIdx.x;
    if (e >= NE) return;
    int d = edst[e];
    int s = esrc[e];
    int pos = atomicAdd(&g_cursor[d], 1);
    float wn = ew[e] * __ldg(&norm[s]);
    int packed = s | (__ldg(&word_ids[s]) << 17);   // src < 2^17, wid < 2^14
    g_meta[pos] = make_int2(packed, __float_as_int(wn));
}

// ---------------- 4: gemm0 -- Ph = half(emb @ W0), inline fp32->fp16 ---------
__global__ __launch_bounds__(128) void gemm0_k(const float* __restrict__ emb) {
    __shared__ __half Ah[64 * DD];   // 16 KB
    int rb = blockIdx.x * 64;
    // convert 64 rows of emb to half in smem (zero-pad past NV)
    for (int i = threadIdx.x; i < 64 * DD; i += 128) {
        int row = rb + (i >> 7);
        Ah[i] = (row < NV) ? __float2half(emb[row * DD + (i & 127)]) : __half(0.f);
    }
    __syncthreads();

    int warp = threadIdx.x >> 5;
    wmma::fragment<wmma::accumulator, 16, 16, 16, float> acc[8];
#pragma unroll
    for (int n = 0; n < 8; n++) wmma::fill_fragment(acc[n], 0.0f);
#pragma unroll
    for (int k = 0; k < 8; k++) {
        wmma::fragment<wmma::matrix_a, 16, 16, 16, __half, wmma::row_major> af;
        wmma::load_matrix_sync(af, Ah + (warp * 16) * DD + k * 16, DD);
#pragma unroll
        for (int n = 0; n < 8; n++) {
            wmma::fragment<wmma::matrix_b, 16, 16, 16, __half, wmma::row_major> bf;
            wmma::load_matrix_sync(bf, g_W0h + (k * 16) * DD + n * 16, DD);
            wmma::mma_sync(acc[n], af, bf, acc[n]);
        }
    }
    __syncthreads();
    float* Out = (float*)Ah;         // reuse (need 64x128 floats? no: per-warp 16x128)
    // store per-warp to global via smem staging per 16-row stripe
    __shared__ float St[64 * 32];    // 8KB staging: each warp 16x128 -> do in 4 chunks
    (void)Out;
#pragma unroll
    for (int n = 0; n < 8; n += 2) {
        wmma::store_matrix_sync(&St[warp * 16 * 32 + 0],  acc[n],     32, wmma::mem_row_major);
        wmma::store_matrix_sync(&St[warp * 16 * 32 + 16], acc[n + 1], 32, wmma::mem_row_major);
        __syncwarp();
        // write 16 rows x 32 cols to g_Ph
        int lane = threadIdx.x & 31;
#pragma unroll
        for (int r = 0; r < 16; r++) {
            int row = rb + warp * 16 + r;
            if (row < NV) {
                float v = St[warp * 16 * 32 + r * 32 + lane];
                g_Ph[row * DD + n * 16 + lane] = __float2half(v);
            }
        }
        __syncwarp();
    }
}

// ---------------- 5: agg0 (warp per dst node) --------------------------------
// acc = sum wn * Ph[wid];  H0h = half(relu(acc*norm[dst] + b0))
__global__ __launch_bounds__(256) void agg0_k(const float* __restrict__ norm,
                                              const float* __restrict__ bias) {
    int node = (blockIdx.x * 256 + threadIdx.x) >> 5;
    if (node >= NN) return;
    int lane = threadIdx.x & 31;
    int beg = g_off[node], end = g_off[node + 1];
    const float2* tbl = (const float2*)g_Ph;

    float ax = 0.f, ay = 0.f, az = 0.f, aw = 0.f;
    int e = beg;
    for (; e + 8 <= end; e += 8) {
        int2 m[8];
#pragma unroll
        for (int j = 0; j < 8; j++) m[j] = __ldg(g_meta + e + j);
        float2 raw[8];
#pragma unroll
        for (int j = 0; j < 8; j++)
            raw[j] = __ldg(tbl + ((unsigned)m[j].x >> 17) * 32 + lane);
#pragma unroll
        for (int j = 0; j < 8; j++) {
            float c = __int_as_float(m[j].y);
            float2 f0, f1; split_h2(raw[j], f0, f1);
            ax = fmaf(c, f0.x, ax); ay = fmaf(c, f0.y, ay);
            az = fmaf(c, f1.x, az); aw = fmaf(c, f1.y, aw);
        }
    }
    for (; e < end; e++) {
        int2 m = __ldg(g_meta + e);
        float2 raw = __ldg(tbl + ((unsigned)m.x >> 17) * 32 + lane);
        float c = __int_as_float(m.y);
        float2 f0, f1; split_h2(raw, f0, f1);
        ax = fmaf(c, f0.x, ax); ay = fmaf(c, f0.y, ay);
        az = fmaf(c, f1.x, az); aw = fmaf(c, f1.y, aw);
    }
    float nd = __ldg(norm + node);
    float4 b = __ldg((const float4*)bias + lane);
    float rx = fmaxf(fmaf(ax, nd, b.x), 0.f);
    float ry = fmaxf(fmaf(ay, nd, b.y), 0.f);
    float rz = fmaxf(fmaf(az, nd, b.z), 0.f);
    float rw = fmaxf(fmaf(aw, nd, b.w), 0.f);
    float2 outp;
    *reinterpret_cast<__half2*>(&outp.x) = __floats2half2_rn(rx, ry);
    *reinterpret_cast<__half2*>(&outp.y) = __floats2half2_rn(rz, rw);
    ((float2*)g_H0h)[node * 32 + lane] = outp;
}

// ---------------- 6: fused agg1 + gemm1 + bias/relu/max-pool -----------------
// block = 512 threads, 64 nodes. Phase 1: warp w aggregates nodes rb+4w..+3
// into smem S (fp16). Phase 2: 64x128x128 wmma from S @ W1h. Phase 3: pool.
__global__ __launch_bounds__(512) void aggemm1_k(const float* __restrict__ norm,
                                                 const float* __restrict__ bias,
                                                 const int* __restrict__ gid) {
    __shared__ float buf[64 * DD];        // 32 KB; first 16 KB doubles as S (half)
    __shared__ float partial[4 * DD];     // 2 KB pooling staging
    __half* S = (__half*)buf;
    int tid = threadIdx.x;
    int warp = tid >> 5;
    int lane = tid & 31;
    int rb = blockIdx.x * 64;
    const float2* tbl = (const float2*)g_H0h;

    // ---- phase 1: aggregate 4 nodes per warp ----
#pragma unroll
    for (int i = 0; i < 4; i++) {
        int row = warp * 4 + i;
        int node = rb + row;
        float ax = 0.f, ay = 0.f, az = 0.f, aw = 0.f;
        if (node < NN) {
            int beg = g_off[node], end = g_off[node + 1];
            int e = beg;
            for (; e + 8 <= end; e += 8) {
                int2 m[8];
#pragma unroll
                for (int j = 0; j < 8; j++) m[j] = __ldg(g_meta + e + j);
                float2 raw[8];
#pragma unroll
                for (int j = 0; j < 8; j++)
                    raw[j] = __ldg(tbl + (m[j].x & 0x1FFFF) * 32 + lane);
#pragma unroll
                for (int j = 0; j < 8; j++) {
                    float c = __int_as_float(m[j].y);
                    float2 f0, f1; split_h2(raw[j], f0, f1);
                    ax = fmaf(c, f0.x, ax); ay = fmaf(c, f0.y, ay);
                    az = fmaf(c, f1.x, az); aw = fmaf(c, f1.y, aw);
                }
            }
            for (; e < end; e++) {
                int2 m = __ldg(g_meta + e);
                float2 raw = __ldg(tbl + (m.x & 0x1FFFF) * 32 + lane);
                float c = __int_as_float(m.y);
                float2 f0, f1; split_h2(raw, f0, f1);
                ax = fmaf(c, f0.x, ax); ay = fmaf(c, f0.y, ay);
                az = fmaf(c, f1.x, az); aw = fmaf(c, f1.y, aw);
            }
            float nd = __ldg(norm + node);
            ax *= nd; ay *= nd; az *= nd; aw *= nd;
        }
        float2 outp;
        *reinterpret_cast<__half2*>(&outp.x) = __floats2half2_rn(ax, ay);
        *reinterpret_cast<__half2*>(&outp.y) = __floats2half2_rn(az, aw);
        ((float2*)S)[row * 32 + lane] = outp;
    }
    __syncthreads();

    // ---- phase 2: wmma 64x128x128. warp w: rows (w>>2)*16, cols (w&3)*32 ----
    int r0 = (warp >> 2) * 16;
    int c0 = (warp & 3) * 32;
    wmma::fragment<wmma::accumulator, 16, 16, 16, float> acc[2];
    wmma::fill_fragment(acc[0], 0.0f);
    wmma::fill_fragment(acc[1], 0.0f);
#pragma unroll
    for (int k = 0; k < 8; k++) {
        wmma::fragment<wmma::matrix_a, 16, 16, 16, __half, wmma::row_major> af;
        wmma::load_matrix_sync(af, S + r0 * DD + k * 16, DD);
#pragma unroll
        for (int n = 0; n < 2; n++) {
            wmma::fragment<wmma::matrix_b, 16, 16, 16, __half, wmma::row_major> bf;
            wmma::load_matrix_sync(bf, g_W1h + (k * 16) * DD + c0 + n * 16, DD);
            wmma::mma_sync(acc[n], af, bf, acc[n]);
        }
    }
    __syncthreads();                       // all reads of S done
    wmma::store_matrix_sync(&buf[r0 * DD + c0],      acc[0], DD, wmma::mem_row_major);
    wmma::store_matrix_sync(&buf[r0 * DD + c0 + 16], acc[1], DD, wmma::mem_row_major);
    __syncthreads();

    // ---- phase 3: bias + relu + per-graph max-pool ----
    int gfirst = __ldg(gid + rb);
    int lastrow = rb + 63; if (lastrow >= NN) lastrow = NN - 1;
    int glast = __ldg(gid + lastrow);
    if (gfirst == glast) {
        int col = tid & 127;
        int q = tid >> 7;                  // 0..3, 16 rows each
        float bv = __ldg(bias + col);
        float m = 0.0f;
#pragma unroll 4
        for (int r = q * 16; r < q * 16 + 16; r++) {
            if (rb + r < NN)
                m = fmaxf(m, fmaxf(buf[r * DD + col] + bv, 0.0f));
        }
        partial[q * DD + col] = m;
        __syncthreads();
        if (tid < DD) {
            float mm = fmaxf(fmaxf(partial[tid], partial[DD + tid]),
                             fmaxf(partial[2 * DD + tid], partial[3 * DD + tid]));
            atomicMax((int*)&g_pool[gfirst * DD + tid], __float_as_int(mm));
        }
    } else {
        if (tid < DD) {
            float bv = __ldg(bias + tid);
            for (int r = 0; r < 64; r++) {
                int row = rb + r;
                if (row < NN) {
                    int gg = __ldg(gid + row);
                    float v = fmaxf(buf[r * DD + tid] + bv, 0.0f);
                    atomicMax((int*)&g_pool[gg * DD + tid], __float_as_int(v));
                }
            }
        }
    }
}

// ---------------- 7: head ----------------------------------------------------
__global__ void k_final(const float* __restrict__ Wout, const float* __restrict__ bout,
                        const float* __restrict__ y, float* __restrict__ out,
                        int out_size) {
    __shared__ float s_loss[NG];
    __shared__ float s_pred[NG];
    int warp = threadIdx.x >> 5;
    int lane = threadIdx.x & 31;
    if (warp < NG) {
        float4 gv = ((const float4*)g_pool)[warp * 32 + lane];
        float4 wv = __ldg((const float4*)Wout + lane);
        float d = gv.x * wv.x + gv.y * wv.y + gv.z * wv.z + gv.w * wv.w;
#pragma unroll
        for (int o = 16; o > 0; o >>= 1) d += __shfl_xor_sync(0xffffffffu, d, o);
        if (lane == 0) {
            float z = d + __ldg(bout);
            float yd = __ldg(y + warp);
            s_loss[warp] = fmaxf(z, 0.f) - z * yd + log1pf(expf(-fabsf(z)));
            s_pred[warp] = 1.f / (1.f + expf(-z));
        }
    }
    __syncthreads();
    if (threadIdx.x == 0) {
        float L = 0.f;
        for (int i = 0; i < NG; i++) L += s_loss[i];
        L *= (1.f / NG);
        if (out_size >= NG + 1) {
            out[0] = L;
            for (int i = 0; i < NG; i++) out[1 + i] = s_pred[i];
            for (int i = NG + 1; i < out_size; i++) out[i] = 0.f;
        } else if (out_size == NG) {
            for (int i = 0; i < NG; i++) out[i] = s_pred[i];
        } else {
            out[0] = L;
        }
    }
}

// ---------------- launch -----------------------------------------------------
extern "C" void kernel_launch(void* const* d_in, const int* in_sizes, int n_in,
                              void* d_out, int out_size) {
    const int*   word_ids = (const int*)d_in[0];
    const int*   esrc     = (const int*)d_in[1];
    const int*   edst     = (const int*)d_in[2];
    const float* ew       = (const float*)d_in[3];
    const float* norm     = (const float*)d_in[4];
    const int*   gid      = (const int*)d_in[5];
    const float* y        = (const float*)d_in[6];
    const float* emb      = (const float*)d_in[7];
    const float* W0       = (const float*)d_in[8];
    const float* b0       = (const float*)d_in[9];
    const float* W1       = (const float*)d_in[10];
    const float* b1       = (const float*)d_in[11];
    const float* Wout     = (const float*)d_in[12];
    const float* bout     = (const float*)d_in[13];
    float* out = (float*)d_out;

    k_zero   <<<(NPAD + 4 + 255) / 256, 256>>>(W0, W1);        // 0
    k_hist   <<<(NE + 255) / 256, 256>>>(edst);                // 1
    k_scan   <<<NSCB, 256>>>();                                // 2
    k_scatter<<<(NE + 255) / 256, 256>>>(esrc, edst, ew, norm, word_ids); // 3
    gemm0_k  <<<(NV + 63) / 64, 128>>>(emb);                   // 4
    agg0_k   <<<(NN + 7) / 8, 256>>>(norm, b0);                // 5  <- ncu slot
    aggemm1_k<<<(NN + 63) / 64, 512>>>(norm, b1, gid);         // 6
    k_final  <<<1, 512>>>(Wout, bout, y, out, out_size);       // 7
}